// round 1
// baseline (speedup 1.0000x reference)
#include <cuda_runtime.h>

// Problem constants
#define Bb 2
#define Hh 16
#define Tt 2048
#define Kk 64
#define Vv 64
#define Cc 32                 // chunk length
#define NCk (Tt/Cc)           // 64 chunks
#define BH (Bb*Hh)            // 32
#define OUT_T_SIZE (BH*Tt*Vv) // 4194304 floats of 'out' before state_f

// ---------------- scratch (static __device__, no allocation) ----------------
__device__ float g_rt[(size_t)BH*Tt*Kk];            // r~ = r * a_{t-1}      16MB
__device__ float g_kt[(size_t)BH*Tt*Kk];            // k~ = k / a_t          16MB
__device__ float g_aC[BH*NCk*Kk];                   // chunk total decay     512KB
__device__ float g_dS[(size_t)BH*NCk*Kk*Vv];        // chunk state delta     33MB
__device__ float g_Sc[(size_t)BH*NCk*Kk*Vv];        // state at chunk start  33MB
__device__ float g_diag[BH*Tt];                     // sum_k r*u*k           256KB

// ---------------- kernel 1: per-chunk decays + delta-state GEMM ----------------
__global__ __launch_bounds__(256) void k1_chunk(
    const float* __restrict__ r, const float* __restrict__ k,
    const float* __restrict__ v, const float* __restrict__ w,
    const float* __restrict__ u)
{
    const int c  = blockIdx.x;
    const int bh = blockIdx.y;
    const int h  = bh & (Hh - 1);
    const int t0 = c * Cc;

    __shared__ float s_kt[Cc][Kk];        // k~ chunk
    __shared__ float s_v[Cc][Vv];         // v chunk
    __shared__ float s_ruk[Cc][Kk + 1];   // r*u*k products (padded)
    __shared__ float s_a[Kk];             // a_C

    const int tid = threadIdx.x;

    // stage v chunk (2048 floats)
    {
        const float4* vp = (const float4*)(v + ((size_t)bh * Tt + t0) * Vv);
        #pragma unroll
        for (int i = tid; i < Cc * Vv / 4; i += 256)
            ((float4*)s_v)[i] = vp[i];
    }

    // cumulative products: one thread per k (threads 0..63)
    if (tid < Kk) {
        const int kk = tid;
        const float* wp = w + ((size_t)h  * Tt + t0) * Kk + kk;
        const float* rp = r + ((size_t)bh * Tt + t0) * Kk + kk;
        const float* kp = k + ((size_t)bh * Tt + t0) * Kk + kk;
        float* rtp = g_rt + ((size_t)bh * Tt + t0) * Kk + kk;
        float* ktp = g_kt + ((size_t)bh * Tt + t0) * Kk + kk;
        const float uk = u[h * Kk + kk];

        float a = 1.0f;
        #pragma unroll
        for (int t = 0; t < Cc; t++) {
            float wv = fmaxf(wp[t * Kk], 1e-6f);  // guard exact-zero w
            float rv = rp[t * Kk];
            float kv = kp[t * Kk];
            float rtil = rv * a;                  // r * a_{t-1}
            a *= wv;
            float ktil = kv / a;                  // k / a_t
            rtp[t * Kk] = rtil;
            ktp[t * Kk] = ktil;
            s_kt[t][kk]  = ktil;
            s_ruk[t][kk] = rv * kv * uk;
        }
        s_a[kk] = a;
        g_aC[(bh * NCk + c) * Kk + kk] = a;
    }
    __syncthreads();

    // diagonal terms d_t = sum_k r*u*k  (threads 0..31)
    if (tid < Cc) {
        float d = 0.0f;
        #pragma unroll
        for (int j = 0; j < Kk; j++) d += s_ruk[tid][j];
        g_diag[bh * Tt + t0 + tid] = d;
    }

    // delta-state GEMM: dS[k][v] = a_C[k] * sum_t k~_t[k] * v_t[v]
    const int tk = (tid >> 4) * 4;
    const int tv = (tid & 15) * 4;
    float acc[4][4];
    #pragma unroll
    for (int i = 0; i < 4; i++)
        #pragma unroll
        for (int j = 0; j < 4; j++) acc[i][j] = 0.0f;

    #pragma unroll
    for (int t = 0; t < Cc; t++) {
        float4 ka = *(const float4*)&s_kt[t][tk];
        float4 va = *(const float4*)&s_v[t][tv];
        float kr[4] = {ka.x, ka.y, ka.z, ka.w};
        float vr[4] = {va.x, va.y, va.z, va.w};
        #pragma unroll
        for (int i = 0; i < 4; i++)
            #pragma unroll
            for (int j = 0; j < 4; j++)
                acc[i][j] = fmaf(kr[i], vr[j], acc[i][j]);
    }

    float* dsp = g_dS + (size_t)(bh * NCk + c) * Kk * Vv;
    #pragma unroll
    for (int i = 0; i < 4; i++) {
        float sc = s_a[tk + i];
        float4 o;
        o.x = acc[i][0] * sc; o.y = acc[i][1] * sc;
        o.z = acc[i][2] * sc; o.w = acc[i][3] * sc;
        *(float4*)&dsp[(size_t)(tk + i) * Vv + tv] = o;
    }
}

// ---------------- kernel 2: sequential chunk-level state scan ----------------
__global__ __launch_bounds__(256) void k2_scan(
    const float* __restrict__ state_in, float* __restrict__ out)
{
    const int bh  = blockIdx.x;
    const int tid = threadIdx.x;

    float4 S[4];
    {
        const float4* si = (const float4*)(state_in + (size_t)bh * Kk * Vv);
        #pragma unroll
        for (int p = 0; p < 4; p++) S[p] = si[p * 256 + tid];
    }

    const float*  aCb = g_aC + bh * NCk * Kk;
    const float4* dSb = (const float4*)(g_dS + (size_t)bh * NCk * Kk * Vv);
    float4*       Scb = (float4*)(g_Sc + (size_t)bh * NCk * Kk * Vv);
    const int krow = tid >> 4;  // k index contribution from tid

    float4 d0[4], d1[4];
    float  a0[4], a1[4];

    #pragma unroll
    for (int p = 0; p < 4; p++) {
        d0[p] = dSb[p * 256 + tid];
        a0[p] = aCb[p * 16 + krow];
    }

    for (int c = 0; c < NCk; c += 2) {
        // prefetch c+1
        {
            const float4* dn = dSb + (size_t)(c + 1) * 1024;
            const float*  an = aCb + (c + 1) * Kk;
            #pragma unroll
            for (int p = 0; p < 4; p++) { d1[p] = dn[p * 256 + tid]; a1[p] = an[p * 16 + krow]; }
        }
        // consume c
        {
            float4* sc = Scb + (size_t)c * 1024;
            #pragma unroll
            for (int p = 0; p < 4; p++) {
                sc[p * 256 + tid] = S[p];
                float a = a0[p]; float4 d = d0[p];
                S[p].x = fmaf(a, S[p].x, d.x); S[p].y = fmaf(a, S[p].y, d.y);
                S[p].z = fmaf(a, S[p].z, d.z); S[p].w = fmaf(a, S[p].w, d.w);
            }
        }
        // prefetch c+2
        if (c + 2 < NCk) {
            const float4* dn = dSb + (size_t)(c + 2) * 1024;
            const float*  an = aCb + (c + 2) * Kk;
            #pragma unroll
            for (int p = 0; p < 4; p++) { d0[p] = dn[p * 256 + tid]; a0[p] = an[p * 16 + krow]; }
        }
        // consume c+1
        {
            float4* sc = Scb + (size_t)(c + 1) * 1024;
            #pragma unroll
            for (int p = 0; p < 4; p++) {
                sc[p * 256 + tid] = S[p];
                float a = a1[p]; float4 d = d1[p];
                S[p].x = fmaf(a, S[p].x, d.x); S[p].y = fmaf(a, S[p].y, d.y);
                S[p].z = fmaf(a, S[p].z, d.z); S[p].w = fmaf(a, S[p].w, d.w);
            }
        }
    }

    // final state -> output
    float4* so = (float4*)(out + (size_t)OUT_T_SIZE + (size_t)bh * Kk * Vv);
    #pragma unroll
    for (int p = 0; p < 4; p++) so[p * 256 + tid] = S[p];
}

// ---------------- kernel 3: outputs (intra-chunk attention + cross term) ----------------
__global__ __launch_bounds__(256) void k3_out(
    const float* __restrict__ v, float* __restrict__ out)
{
    const int c  = blockIdx.x;
    const int bh = blockIdx.y;
    const int t0 = c * Cc;

    __shared__ float s_S[Kk][Vv];        // chunk-start state (16KB)
    __shared__ float s_rt[Cc][68];       // r~ chunk, padded (8.5KB)
    __shared__ float s_ktT[Kk][36];      // k~ chunk transposed, padded (9KB)
    __shared__ float s_v[Cc][Vv];        // v chunk (8KB)
    __shared__ float s_P[Cc][36];        // masked attention matrix (4.5KB)
    __shared__ float s_diag[Cc];

    const int tid = threadIdx.x;

    // stage chunk-start state
    {
        const float4* Sp = (const float4*)(g_Sc + (size_t)(bh * NCk + c) * Kk * Vv);
        #pragma unroll
        for (int p = 0; p < 4; p++) {
            float4 x = Sp[p * 256 + tid];
            int f = p * 256 + tid;             // float4 index
            int kr = f >> 4, v0 = (f & 15) * 4;
            *(float4*)&s_S[kr][v0] = x;
        }
    }
    // stage r~ (row-major, padded rows)
    {
        const float4* rp = (const float4*)(g_rt + ((size_t)bh * Tt + t0) * Kk);
        #pragma unroll
        for (int i = tid; i < Cc * Kk / 4; i += 256) {
            float4 x = rp[i];
            int t = i >> 4, k0 = (i & 15) * 4;
            *(float4*)&s_rt[t][k0] = x;
        }
    }
    // stage v
    {
        const float4* vp = (const float4*)(v + ((size_t)bh * Tt + t0) * Vv);
        #pragma unroll
        for (int i = tid; i < Cc * Vv / 4; i += 256)
            ((float4*)s_v)[i] = vp[i];
    }
    // stage k~ transposed
    {
        const float4* kp = (const float4*)(g_kt + ((size_t)bh * Tt + t0) * Kk);
        #pragma unroll
        for (int i = tid; i < Cc * Kk / 4; i += 256) {
            float4 x = kp[i];
            int t = i >> 4, k0 = (i & 15) * 4;
            s_ktT[k0 + 0][t] = x.x;
            s_ktT[k0 + 1][t] = x.y;
            s_ktT[k0 + 2][t] = x.z;
            s_ktT[k0 + 3][t] = x.w;
        }
    }
    if (tid < Cc) s_diag[tid] = g_diag[bh * Tt + t0 + tid];
    __syncthreads();

    // GEMM1: P[t][tau] = sum_k r~_t[k] * k~_tau[k], then causal mask + diag
    {
        const int t    = tid >> 3;
        const int tau0 = (tid & 7) * 4;
        float acc[4] = {0.f, 0.f, 0.f, 0.f};
        #pragma unroll
        for (int kk = 0; kk < Kk; kk++) {
            float rv = s_rt[t][kk];
            float4 kt4 = *(const float4*)&s_ktT[kk][tau0];
            acc[0] = fmaf(rv, kt4.x, acc[0]);
            acc[1] = fmaf(rv, kt4.y, acc[1]);
            acc[2] = fmaf(rv, kt4.z, acc[2]);
            acc[3] = fmaf(rv, kt4.w, acc[3]);
        }
        float dg = s_diag[t];
        #pragma unroll
        for (int j = 0; j < 4; j++) {
            int ta = tau0 + j;
            s_P[t][ta] = (ta < t) ? acc[j] : ((ta == t) ? dg : 0.0f);
        }
    }
    __syncthreads();

    // GEMM2: O[t][v] = sum_k r~_t[k]*S[k][v] + sum_tau P[t][tau]*v_tau[v]
    const int t2 = (tid >> 4) * 2;
    const int v4 = (tid & 15) * 4;
    float a0[4] = {0.f, 0.f, 0.f, 0.f};
    float a1[4] = {0.f, 0.f, 0.f, 0.f};

    #pragma unroll
    for (int kk = 0; kk < Kk; kk++) {
        float r0 = s_rt[t2][kk];
        float r1 = s_rt[t2 + 1][kk];
        float4 sv = *(const float4*)&s_S[kk][v4];
        a0[0] = fmaf(r0, sv.x, a0[0]); a0[1] = fmaf(r0, sv.y, a0[1]);
        a0[2] = fmaf(r0, sv.z, a0[2]); a0[3] = fmaf(r0, sv.w, a0[3]);
        a1[0] = fmaf(r1, sv.x, a1[0]); a1[1] = fmaf(r1, sv.y, a1[1]);
        a1[2] = fmaf(r1, sv.z, a1[2]); a1[3] = fmaf(r1, sv.w, a1[3]);
    }
    #pragma unroll
    for (int ta = 0; ta < Cc; ta++) {
        float p0 = s_P[t2][ta];
        float p1 = s_P[t2 + 1][ta];
        float4 vv = *(const float4*)&s_v[ta][v4];
        a0[0] = fmaf(p0, vv.x, a0[0]); a0[1] = fmaf(p0, vv.y, a0[1]);
        a0[2] = fmaf(p0, vv.z, a0[2]); a0[3] = fmaf(p0, vv.w, a0[3]);
        a1[0] = fmaf(p1, vv.x, a1[0]); a1[1] = fmaf(p1, vv.y, a1[1]);
        a1[2] = fmaf(p1, vv.z, a1[2]); a1[3] = fmaf(p1, vv.w, a1[3]);
    }

    float* op = out + ((size_t)bh * Tt + t0) * Vv;
    *(float4*)&op[(size_t)t2 * Vv + v4]       = make_float4(a0[0], a0[1], a0[2], a0[3]);
    *(float4*)&op[(size_t)(t2 + 1) * Vv + v4] = make_float4(a1[0], a1[1], a1[2], a1[3]);
}

// ---------------- launch ----------------
extern "C" void kernel_launch(void* const* d_in, const int* in_sizes, int n_in,
                              void* d_out, int out_size)
{
    const float* r  = (const float*)d_in[0];
    const float* k  = (const float*)d_in[1];
    const float* v  = (const float*)d_in[2];
    const float* w  = (const float*)d_in[3];
    const float* u  = (const float*)d_in[4];
    const float* st = (const float*)d_in[5];
    float* out = (float*)d_out;

    k1_chunk<<<dim3(NCk, BH), 256>>>(r, k, v, w, u);
    k2_scan<<<BH, 256>>>(st, out);
    k3_out<<<dim3(NCk, BH), 256>>>(v, out);
}

// round 3
// speedup vs baseline: 1.3541x; 1.3541x over previous
#include <cuda_runtime.h>

// Problem constants
#define Bb 2
#define Hh 16
#define Tt 2048
#define Kk 64
#define Vv 64
#define Cc 32                 // chunk length
#define NCk (Tt/Cc)           // 64 chunks
#define BH (Bb*Hh)            // 32
#define OUT_T_SIZE (BH*Tt*Vv) // floats of 'out' before state_f

// ---------------- scratch (static __device__, no allocation) ----------------
__device__ float g_aC[BH*NCk*Kk];                   // chunk total decay     512KB
__device__ float g_dS[(size_t)BH*NCk*Kk*Vv];        // chunk state delta     33MB
__device__ float g_Sc[(size_t)BH*NCk*Kk*Vv];        // state at chunk start  33MB

// Warp-inclusive product scan over lanes (lane = t)
__device__ __forceinline__ float warp_prod_scan(float a) {
    #pragma unroll
    for (int off = 1; off < 32; off <<= 1) {
        float x = __shfl_up_sync(0xffffffffu, a, off);
        if ((threadIdx.x & 31) >= off) a *= x;
    }
    return a;
}

// ---------------- kernel 1: per-chunk decays + delta-state GEMM ----------------
__global__ __launch_bounds__(256) void k1_chunk(
    const float* __restrict__ k, const float* __restrict__ v,
    const float* __restrict__ w)
{
    const int c  = blockIdx.x;
    const int bh = blockIdx.y;
    const int h  = bh & (Hh - 1);
    const int t0 = c * Cc;

    __shared__ float s_w[Cc][68];   // staged w (padded; 16B-aligned rows)
    __shared__ float s_k[Cc][68];   // raw k, overwritten in-place with k~
    __shared__ float s_v[Cc][Vv];
    __shared__ float s_a[Kk];       // a_C

    const int tid  = threadIdx.x;
    const int lane = tid & 31;
    const int wi   = tid >> 5;

    // ---- stage w, k, v (coalesced float4) ----
    {
        const float4* wp = (const float4*)(w + ((size_t)h  * Tt + t0) * Kk);
        const float4* kp = (const float4*)(k + ((size_t)bh * Tt + t0) * Kk);
        const float4* vp = (const float4*)(v + ((size_t)bh * Tt + t0) * Vv);
        #pragma unroll
        for (int i = tid; i < Cc * Kk / 4; i += 256) {
            int t = i >> 4, k0 = (i & 15) * 4;
            *(float4*)&s_w[t][k0] = wp[i];
            *(float4*)&s_k[t][k0] = kp[i];
            ((float4*)s_v)[i]     = vp[i];
        }
    }
    __syncthreads();

    // ---- shuffle scan: lane = t, each warp owns 8 k columns ----
    #pragma unroll
    for (int i = 0; i < 8; i++) {
        const int kk = wi * 8 + i;
        float wv = fmaxf(s_w[lane][kk], 1e-6f);
        float a  = warp_prod_scan(wv);         // a_t = prod_{0..t} w
        float ktil = s_k[lane][kk] / a;        // k~ = k / a_t
        s_k[lane][kk] = ktil;
        if (lane == 31) {
            s_a[kk] = a;
            g_aC[(bh * NCk + c) * Kk + kk] = a;
        }
    }
    __syncthreads();

    // ---- delta-state GEMM: dS[k][v] = a_C[k] * sum_t k~_t[k] * v_t[v] ----
    const int tk = (tid >> 4) * 4;
    const int tv = (tid & 15) * 4;
    float acc[4][4];
    #pragma unroll
    for (int i = 0; i < 4; i++)
        #pragma unroll
        for (int j = 0; j < 4; j++) acc[i][j] = 0.0f;

    #pragma unroll
    for (int t = 0; t < Cc; t++) {
        float4 ka = *(const float4*)&s_k[t][tk];
        float4 va = *(const float4*)&s_v[t][tv];
        float kr[4] = {ka.x, ka.y, ka.z, ka.w};
        float vr[4] = {va.x, va.y, va.z, va.w};
        #pragma unroll
        for (int i = 0; i < 4; i++)
            #pragma unroll
            for (int j = 0; j < 4; j++)
                acc[i][j] = fmaf(kr[i], vr[j], acc[i][j]);
    }

    float* dsp = g_dS + (size_t)(bh * NCk + c) * Kk * Vv;
    #pragma unroll
    for (int i = 0; i < 4; i++) {
        float sc = s_a[tk + i];
        float4 o;
        o.x = acc[i][0] * sc; o.y = acc[i][1] * sc;
        o.z = acc[i][2] * sc; o.w = acc[i][3] * sc;
        *(float4*)&dsp[(size_t)(tk + i) * Vv + tv] = o;
    }
}

// ---------------- kernel 2: sequential chunk-level state scan ----------------
// Parallel over (bh, quarter of the 64x64 state). Each thread owns ONE float4.
__global__ __launch_bounds__(256) void k2_scan(
    const float* __restrict__ state_in, float* __restrict__ out)
{
    const int bh  = blockIdx.y;
    const int tid = threadIdx.x;
    const int fi  = blockIdx.x * 256 + tid;    // float4 index in [0,1024)
    const int krow = fi >> 4;                  // k row (16 float4 per row)

    float4 S = ((const float4*)(state_in + (size_t)bh * Kk * Vv))[fi];

    const float*  aCb = g_aC + bh * NCk * Kk;
    const float4* dSb = (const float4*)(g_dS + (size_t)bh * NCk * Kk * Vv);
    float4*       Scb = (float4*)(g_Sc + (size_t)bh * NCk * Kk * Vv);

    float4 db[2][4];
    float  ab[2][4];

    // prefetch group 0
    #pragma unroll
    for (int j = 0; j < 4; j++) {
        db[0][j] = dSb[(size_t)j * 1024 + fi];
        ab[0][j] = aCb[j * Kk + krow];
    }

    #pragma unroll 1
    for (int g = 0; g < NCk / 4; g++) {
        const int cur = g & 1;
        // prefetch next group of 4 chunks
        if (g + 1 < NCk / 4) {
            #pragma unroll
            for (int j = 0; j < 4; j++) {
                int c = (g + 1) * 4 + j;
                db[cur ^ 1][j] = dSb[(size_t)c * 1024 + fi];
                ab[cur ^ 1][j] = aCb[c * Kk + krow];
            }
        }
        // consume current group
        #pragma unroll
        for (int j = 0; j < 4; j++) {
            int c = g * 4 + j;
            Scb[(size_t)c * 1024 + fi] = S;
            float a = ab[cur][j]; float4 d = db[cur][j];
            S.x = fmaf(a, S.x, d.x); S.y = fmaf(a, S.y, d.y);
            S.z = fmaf(a, S.z, d.z); S.w = fmaf(a, S.w, d.w);
        }
    }

    // final state -> output tail
    ((float4*)(out + (size_t)OUT_T_SIZE + (size_t)bh * Kk * Vv))[fi] = S;
}

// ---------------- kernel 3: outputs (recompute r~/k~/diag, two GEMMs) ----------------
// Dynamic shared memory (exceeds the 48KB static limit).
struct K3Smem {
    float S[Kk][Vv];         // chunk-start state (16384 B)
    float rt[Cc][68];        // raw r -> r~ in place (8704 B)
    float ktT[Kk][36];       // raw k (transposed) -> k~ in place (9216 B)
    float v[Cc][Vv];         // v chunk (8192 B)
    union {                  // w needed only before GEMM1; P only after
        float w[Cc][68];
        float P[Cc][36];
    } wp;                    // (8704 B)
    float dp[8][33];         // per-warp diag partials (1056 B)
    float diag[Cc];          // (128 B)
};

__global__ __launch_bounds__(256) void k3_out(
    const float* __restrict__ r, const float* __restrict__ k,
    const float* __restrict__ v, const float* __restrict__ w,
    const float* __restrict__ u, float* __restrict__ out)
{
    extern __shared__ char smem_raw[];
    K3Smem& sm = *reinterpret_cast<K3Smem*>(smem_raw);

    const int c  = blockIdx.x;
    const int bh = blockIdx.y;
    const int h  = bh & (Hh - 1);
    const int t0 = c * Cc;

    const int tid  = threadIdx.x;
    const int lane = tid & 31;
    const int wi   = tid >> 5;

    // ---- stage chunk-start state ----
    {
        const float4* Sp = (const float4*)(g_Sc + (size_t)(bh * NCk + c) * Kk * Vv);
        #pragma unroll
        for (int p = 0; p < 4; p++) {
            float4 x = Sp[p * 256 + tid];
            int f = p * 256 + tid;
            int kr = f >> 4, v0 = (f & 15) * 4;
            *(float4*)&sm.S[kr][v0] = x;
        }
    }
    // ---- stage r, w, v, k(transposed) ----
    {
        const float4* rp = (const float4*)(r + ((size_t)bh * Tt + t0) * Kk);
        const float4* wp = (const float4*)(w + ((size_t)h  * Tt + t0) * Kk);
        const float4* vp = (const float4*)(v + ((size_t)bh * Tt + t0) * Vv);
        const float4* kp = (const float4*)(k + ((size_t)bh * Tt + t0) * Kk);
        #pragma unroll
        for (int i = tid; i < Cc * Kk / 4; i += 256) {
            int t = i >> 4, k0 = (i & 15) * 4;
            *(float4*)&sm.rt[t][k0]   = rp[i];
            *(float4*)&sm.wp.w[t][k0] = wp[i];
            ((float4*)sm.v)[i]        = vp[i];
            float4 x = kp[i];
            sm.ktT[k0 + 0][t] = x.x;
            sm.ktT[k0 + 1][t] = x.y;
            sm.ktT[k0 + 2][t] = x.z;
            sm.ktT[k0 + 3][t] = x.w;
        }
    }
    __syncthreads();

    // ---- shuffle scan: recompute r~, k~, diag partials in-block ----
    {
        float dpart = 0.0f;
        #pragma unroll
        for (int i = 0; i < 8; i++) {
            const int kk = wi * 8 + i;
            float wv = fmaxf(sm.wp.w[lane][kk], 1e-6f);
            float a  = warp_prod_scan(wv);                 // a_t
            float ap = __shfl_up_sync(0xffffffffu, a, 1);  // a_{t-1}
            if (lane == 0) ap = 1.0f;
            float rv = sm.rt[lane][kk];
            float kv = sm.ktT[kk][lane];
            dpart = fmaf(rv * kv, u[h * Kk + kk], dpart);  // diag partial
            sm.rt[lane][kk]  = rv * ap;                    // r~
            sm.ktT[kk][lane] = kv / a;                     // k~
        }
        sm.dp[wi][lane] = dpart;
    }
    __syncthreads();
    if (tid < Cc) {
        float d = 0.0f;
        #pragma unroll
        for (int j = 0; j < 8; j++) d += sm.dp[j][tid];
        sm.diag[tid] = d;
    }
    __syncthreads();

    // ---- GEMM1: P[t][tau] = r~_t . k~_tau, causal mask + diag ----
    {
        const int t    = tid >> 3;
        const int tau0 = (tid & 7) * 4;
        float acc[4] = {0.f, 0.f, 0.f, 0.f};
        #pragma unroll
        for (int kk = 0; kk < Kk; kk++) {
            float rv = sm.rt[t][kk];
            float4 kt4 = *(const float4*)&sm.ktT[kk][tau0];
            acc[0] = fmaf(rv, kt4.x, acc[0]);
            acc[1] = fmaf(rv, kt4.y, acc[1]);
            acc[2] = fmaf(rv, kt4.z, acc[2]);
            acc[3] = fmaf(rv, kt4.w, acc[3]);
        }
        float dg = sm.diag[t];
        float res[4];
        #pragma unroll
        for (int j = 0; j < 4; j++) {
            int ta = tau0 + j;
            res[j] = (ta < t) ? acc[j] : ((ta == t) ? dg : 0.0f);
        }
        __syncthreads();   // P overlaps w (finished reads)
        #pragma unroll
        for (int j = 0; j < 4; j++) sm.wp.P[t][tau0 + j] = res[j];
    }
    __syncthreads();

    // ---- GEMM2: O[t][v] = r~_t . S[:,v] + P[t,:] . v[:,v] ----
    const int t2 = (tid >> 4) * 2;
    const int v4 = (tid & 15) * 4;
    float a0[4] = {0.f, 0.f, 0.f, 0.f};
    float a1[4] = {0.f, 0.f, 0.f, 0.f};

    #pragma unroll
    for (int kk = 0; kk < Kk; kk++) {
        float r0 = sm.rt[t2][kk];
        float r1 = sm.rt[t2 + 1][kk];
        float4 sv = *(const float4*)&sm.S[kk][v4];
        a0[0] = fmaf(r0, sv.x, a0[0]); a0[1] = fmaf(r0, sv.y, a0[1]);
        a0[2] = fmaf(r0, sv.z, a0[2]); a0[3] = fmaf(r0, sv.w, a0[3]);
        a1[0] = fmaf(r1, sv.x, a1[0]); a1[1] = fmaf(r1, sv.y, a1[1]);
        a1[2] = fmaf(r1, sv.z, a1[2]); a1[3] = fmaf(r1, sv.w, a1[3]);
    }
    #pragma unroll
    for (int ta = 0; ta < Cc; ta++) {
        float p0 = sm.wp.P[t2][ta];
        float p1 = sm.wp.P[t2 + 1][ta];
        float4 vv = *(const float4*)&sm.v[ta][v4];
        a0[0] = fmaf(p0, vv.x, a0[0]); a0[1] = fmaf(p0, vv.y, a0[1]);
        a0[2] = fmaf(p0, vv.z, a0[2]); a0[3] = fmaf(p0, vv.w, a0[3]);
        a1[0] = fmaf(p1, vv.x, a1[0]); a1[1] = fmaf(p1, vv.y, a1[1]);
        a1[2] = fmaf(p1, vv.z, a1[2]); a1[3] = fmaf(p1, vv.w, a1[3]);
    }

    float* op = out + ((size_t)bh * Tt + t0) * Vv;
    *(float4*)&op[(size_t)t2 * Vv + v4]       = make_float4(a0[0], a0[1], a0[2], a0[3]);
    *(float4*)&op[(size_t)(t2 + 1) * Vv + v4] = make_float4(a1[0], a1[1], a1[2], a1[3]);
}

// ---------------- launch ----------------
extern "C" void kernel_launch(void* const* d_in, const int* in_sizes, int n_in,
                              void* d_out, int out_size)
{
    const float* r  = (const float*)d_in[0];
    const float* k  = (const float*)d_in[1];
    const float* v  = (const float*)d_in[2];
    const float* w  = (const float*)d_in[3];
    const float* u  = (const float*)d_in[4];
    const float* st = (const float*)d_in[5];
    float* out = (float*)d_out;

    // Raise dynamic smem limit for k3 (config call, not an allocation;
    // executed at capture time only — free at graph replay).
    static bool configured = false;
    if (!configured) {
        cudaFuncSetAttribute(k3_out, cudaFuncAttributeMaxDynamicSharedMemorySize,
                             (int)sizeof(K3Smem));
        configured = true;
    }

    k1_chunk<<<dim3(NCk, BH), 256>>>(k, v, w);
    k2_scan<<<dim3(4, BH), 256>>>(st, out);
    k3_out<<<dim3(NCk, BH), 256, sizeof(K3Smem)>>>(r, k, v, w, u, out);
}

// round 4
// speedup vs baseline: 1.4520x; 1.0723x over previous
#include <cuda_runtime.h>

// Problem constants
#define Bb 2
#define Hh 16
#define Tt 2048
#define Kk 64
#define Vv 64
#define Cc 64                 // chunk length
#define NCk (Tt/Cc)           // 32 chunks
#define BH (Bb*Hh)            // 32
#define OUT_T_SIZE (BH*Tt*Vv) // floats of 'out' before state_f

// ---------------- scratch (static __device__, no allocation) ----------------
__device__ float g_aC[BH*NCk*Kk];                   // chunk total decay     256KB
__device__ float g_dS[(size_t)BH*NCk*Kk*Vv];        // chunk state delta     16MB
__device__ float g_Sc[(size_t)BH*NCk*Kk*Vv];        // state at chunk start  16MB

// Warp-inclusive product scan over lanes
__device__ __forceinline__ float warp_prod_scan(float a) {
    #pragma unroll
    for (int off = 1; off < 32; off <<= 1) {
        float x = __shfl_up_sync(0xffffffffu, a, off);
        if ((threadIdx.x & 31) >= off) a *= x;
    }
    return a;
}

// ================= kernel 1: suffix decays + delta-state GEMM =================
// dS[k][v] = sum_i sfx_i[k] * k_i[k] * v_i[v],  sfx_i = prod_{j=i+1..63} w_j  (<=1, safe)
struct K1Smem {
    float w[Cc][68];
    float k[Cc][68];   // raw k -> sfx*k in place
    float v[Cc][Vv];
};

__global__ __launch_bounds__(256) void k1_chunk(
    const float* __restrict__ k, const float* __restrict__ v,
    const float* __restrict__ w)
{
    extern __shared__ char smem_raw[];
    K1Smem& sm = *reinterpret_cast<K1Smem*>(smem_raw);

    const int c  = blockIdx.x;
    const int bh = blockIdx.y;
    const int h  = bh & (Hh - 1);
    const int t0 = c * Cc;

    const int tid  = threadIdx.x;
    const int lane = tid & 31;
    const int wi   = tid >> 5;

    // ---- stage w, k, v (coalesced float4) ----
    {
        const float4* wp = (const float4*)(w + ((size_t)h  * Tt + t0) * Kk);
        const float4* kp = (const float4*)(k + ((size_t)bh * Tt + t0) * Kk);
        const float4* vp = (const float4*)(v + ((size_t)bh * Tt + t0) * Vv);
        #pragma unroll
        for (int i = tid; i < Cc * Kk / 4; i += 256) {
            int t = i >> 4, k0 = (i & 15) * 4;
            *(float4*)&sm.w[t][k0] = wp[i];
            *(float4*)&sm.k[t][k0] = kp[i];
            ((float4*)sm.v)[i]     = vp[i];
        }
    }
    __syncthreads();

    // ---- two-level suffix scan: each warp owns 8 k-columns ----
    #pragma unroll
    for (int i = 0; i < 8; i++) {
        const int kk = wi * 8 + i;
        // rows 63..32 (reversed)
        float yA = fmaxf(sm.w[63 - lane][kk], 1e-6f);
        float sA = warp_prod_scan(yA);                       // prod rows [63-lane .. 63]
        float sfxA = __shfl_up_sync(0xffffffffu, sA, 1);
        if (lane == 0) sfxA = 1.0f;                          // sfx_{63-lane}
        float T0 = __shfl_sync(0xffffffffu, sA, 31);         // prod rows [32..63]
        sm.k[63 - lane][kk] *= sfxA;
        // rows 31..0 (reversed)
        float yB = fmaxf(sm.w[31 - lane][kk], 1e-6f);
        float sB = warp_prod_scan(yB);                       // prod rows [31-lane .. 31]
        float sfxB = __shfl_up_sync(0xffffffffu, sB, 1);
        if (lane == 0) sfxB = 1.0f;
        sm.k[31 - lane][kk] *= sfxB * T0;                    // sfx_{31-lane}
        if (lane == 31)
            g_aC[(bh * NCk + c) * Kk + kk] = sB * T0;        // full-chunk product
    }
    __syncthreads();

    // ---- delta-state GEMM (64k x 64v over 64t), 4x4 tile per thread ----
    const int tk = (tid >> 4) * 4;
    const int tv = (tid & 15) * 4;
    float acc[4][4];
    #pragma unroll
    for (int a = 0; a < 4; a++)
        #pragma unroll
        for (int b = 0; b < 4; b++) acc[a][b] = 0.0f;

    #pragma unroll 8
    for (int t = 0; t < Cc; t++) {
        float4 ka = *(const float4*)&sm.k[t][tk];
        float4 va = *(const float4*)&sm.v[t][tv];
        float kr[4] = {ka.x, ka.y, ka.z, ka.w};
        float vr[4] = {va.x, va.y, va.z, va.w};
        #pragma unroll
        for (int a = 0; a < 4; a++)
            #pragma unroll
            for (int b = 0; b < 4; b++)
                acc[a][b] = fmaf(kr[a], vr[b], acc[a][b]);
    }

    float* dsp = g_dS + (size_t)(bh * NCk + c) * Kk * Vv;
    #pragma unroll
    for (int a = 0; a < 4; a++)
        *(float4*)&dsp[(size_t)(tk + a) * Vv + tv] =
            make_float4(acc[a][0], acc[a][1], acc[a][2], acc[a][3]);
}

// ================= kernel 2: sequential chunk-level state scan =================
__global__ __launch_bounds__(256) void k2_scan(
    const float* __restrict__ state_in, float* __restrict__ out)
{
    const int bh  = blockIdx.y;
    const int tid = threadIdx.x;
    const int fi  = blockIdx.x * 256 + tid;    // float4 index in [0,1024)
    const int krow = fi >> 4;

    float4 S = ((const float4*)(state_in + (size_t)bh * Kk * Vv))[fi];

    const float*  aCb = g_aC + bh * NCk * Kk;
    const float4* dSb = (const float4*)(g_dS + (size_t)bh * NCk * Kk * Vv);
    float4*       Scb = (float4*)(g_Sc + (size_t)bh * NCk * Kk * Vv);

    float4 db[2][4];
    float  ab[2][4];

    #pragma unroll
    for (int j = 0; j < 4; j++) {
        db[0][j] = dSb[(size_t)j * 1024 + fi];
        ab[0][j] = aCb[j * Kk + krow];
    }

    #pragma unroll 1
    for (int g = 0; g < NCk / 4; g++) {
        const int cur = g & 1;
        if (g + 1 < NCk / 4) {
            #pragma unroll
            for (int j = 0; j < 4; j++) {
                int c = (g + 1) * 4 + j;
                db[cur ^ 1][j] = dSb[(size_t)c * 1024 + fi];
                ab[cur ^ 1][j] = aCb[c * Kk + krow];
            }
        }
        #pragma unroll
        for (int j = 0; j < 4; j++) {
            int c = g * 4 + j;
            Scb[(size_t)c * 1024 + fi] = S;
            float a = ab[cur][j]; float4 d = db[cur][j];
            S.x = fmaf(a, S.x, d.x); S.y = fmaf(a, S.y, d.y);
            S.z = fmaf(a, S.z, d.z); S.w = fmaf(a, S.w, d.w);
        }
    }

    ((float4*)(out + (size_t)OUT_T_SIZE + (size_t)bh * Kk * Vv))[fi] = S;
}

// ================= kernel 3: outputs =================
// Mid-chunk normalization m = prod(rows 0..31):
//   r~_i = r_i * prefix_i                     (<=1; for cross-chunk S term)
//   r^_i = r~_i / m                           (bounded ~e^32)
//   k^_j = k_j * m / incl_j                   (bounded ~e^32)
//   P[i][j] = r^_i . k^_j  (j<i),  diag_i (j==i),  0 (j>i)
//   O = r~ . S  +  P . v
struct K3Smem {
    float S[Kk][Vv];                         // 16384
    float v[Cc][Vv];                         // 16384
    float rT[Kk][68];                        // raw r -> r~ (k-major)
    float rhT[Kk][68];                       // r^
    float kT[Kk][68];                        // raw k -> k^
    union { float wT[Kk][68]; float PT[Cc][68]; } wp;  // w before GEMM1; P^T after
    float dp[8][66];                         // per-warp diag partials
    float diag[Cc];
};

__global__ __launch_bounds__(256) void k3_out(
    const float* __restrict__ r, const float* __restrict__ k,
    const float* __restrict__ v, const float* __restrict__ w,
    const float* __restrict__ u, float* __restrict__ out)
{
    extern __shared__ char smem_raw[];
    K3Smem& sm = *reinterpret_cast<K3Smem*>(smem_raw);

    const int c  = blockIdx.x;
    const int bh = blockIdx.y;
    const int h  = bh & (Hh - 1);
    const int t0 = c * Cc;

    const int tid  = threadIdx.x;
    const int lane = tid & 31;
    const int wi   = tid >> 5;

    // ---- stage chunk-start state ----
    {
        const float4* Sp = (const float4*)(g_Sc + (size_t)(bh * NCk + c) * Kk * Vv);
        #pragma unroll
        for (int p = 0; p < 4; p++) {
            int f = p * 256 + tid;
            float4 x = Sp[f];
            int kr = f >> 4, v0 = (f & 15) * 4;
            *(float4*)&sm.S[kr][v0] = x;
        }
    }
    // ---- stage r,k,w transposed (k-major) + v row-major ----
    {
        const float4* rp = (const float4*)(r + ((size_t)bh * Tt + t0) * Kk);
        const float4* kp = (const float4*)(k + ((size_t)bh * Tt + t0) * Kk);
        const float4* wp = (const float4*)(w + ((size_t)h  * Tt + t0) * Kk);
        const float4* vp = (const float4*)(v + ((size_t)bh * Tt + t0) * Vv);
        #pragma unroll
        for (int i = tid; i < Cc * Kk / 4; i += 256) {
            int t = i >> 4, k0 = (i & 15) * 4;
            float4 rx = rp[i], kx = kp[i], wx = wp[i];
            ((float4*)sm.v)[i] = vp[i];
            sm.rT[k0 + 0][t] = rx.x; sm.rT[k0 + 1][t] = rx.y;
            sm.rT[k0 + 2][t] = rx.z; sm.rT[k0 + 3][t] = rx.w;
            sm.kT[k0 + 0][t] = kx.x; sm.kT[k0 + 1][t] = kx.y;
            sm.kT[k0 + 2][t] = kx.z; sm.kT[k0 + 3][t] = kx.w;
            sm.wp.wT[k0 + 0][t] = wx.x; sm.wp.wT[k0 + 1][t] = wx.y;
            sm.wp.wT[k0 + 2][t] = wx.z; sm.wp.wT[k0 + 3][t] = wx.w;
        }
    }
    __syncthreads();

    // ---- two-level prefix scan + normalize (each warp owns 8 k-columns) ----
    {
        float dA = 0.0f, dB = 0.0f;
        #pragma unroll
        for (int i = 0; i < 8; i++) {
            const int kk = wi * 8 + i;
            const float uk = u[h * Kk + kk];
            // half 0: rows 0..31
            float w0 = fmaxf(sm.wp.wT[kk][lane], 1e-6f);
            float p  = warp_prod_scan(w0);                    // incl_lane = prod rows 0..lane
            float m  = __shfl_sync(0xffffffffu, p, 31);       // prod rows 0..31
            float pre = __shfl_up_sync(0xffffffffu, p, 1);
            if (lane == 0) pre = 1.0f;                        // prefix_lane
            float rv = sm.rT[kk][lane];
            float kv = sm.kT[kk][lane];
            dA = fmaf(rv * kv, uk, dA);
            float rt_ = rv * pre;
            sm.rT[kk][lane]  = rt_;
            sm.rhT[kk][lane] = rt_ / m;
            sm.kT[kk][lane]  = kv * m / p;
            // half 1: rows 32..63
            float w1 = fmaxf(sm.wp.wT[kk][32 + lane], 1e-6f);
            float q  = warp_prod_scan(w1);                    // prod rows 32..32+lane
            float pre2 = __shfl_up_sync(0xffffffffu, q, 1);
            if (lane == 0) pre2 = 1.0f;
            float rv2 = sm.rT[kk][32 + lane];
            float kv2 = sm.kT[kk][32 + lane];
            dB = fmaf(rv2 * kv2, uk, dB);
            sm.rT[kk][32 + lane]  = rv2 * (m * pre2);         // r~
            sm.rhT[kk][32 + lane] = rv2 * pre2;               // r~/m
            sm.kT[kk][32 + lane]  = kv2 / q;                  // k*m/(m*q)
        }
        sm.dp[wi][lane]      = dA;
        sm.dp[wi][32 + lane] = dB;
    }
    __syncthreads();
    if (tid < Cc) {
        float d = 0.0f;
        #pragma unroll
        for (int j = 0; j < 8; j++) d += sm.dp[j][tid];
        sm.diag[tid] = d;
    }
    __syncthreads();

    // ---- GEMM1: P[i][j] = r^_i . k^_j  (4x4 tile), store masked as PT[j][i] ----
    {
        const int i4 = (tid >> 4) * 4;      // t rows
        const int j4 = (tid & 15) * 4;      // tau cols
        float acc[4][4];
        #pragma unroll
        for (int a = 0; a < 4; a++)
            #pragma unroll
            for (int b = 0; b < 4; b++) acc[a][b] = 0.0f;

        #pragma unroll 8
        for (int kk = 0; kk < Kk; kk++) {
            float4 ra = *(const float4*)&sm.rhT[kk][i4];
            float4 kb = *(const float4*)&sm.kT[kk][j4];
            float rr[4] = {ra.x, ra.y, ra.z, ra.w};
            float kc[4] = {kb.x, kb.y, kb.z, kb.w};
            #pragma unroll
            for (int a = 0; a < 4; a++)
                #pragma unroll
                for (int b = 0; b < 4; b++)
                    acc[a][b] = fmaf(rr[a], kc[b], acc[a][b]);
        }
        float dg[4];
        #pragma unroll
        for (int a = 0; a < 4; a++) dg[a] = sm.diag[i4 + a];
        #pragma unroll
        for (int b = 0; b < 4; b++) {
            int j = j4 + b;
            float vals[4];
            #pragma unroll
            for (int a = 0; a < 4; a++) {
                int i = i4 + a;
                vals[a] = (j < i) ? acc[a][b] : ((j == i) ? dg[a] : 0.0f);
            }
            *(float4*)&sm.wp.PT[j][i4] = make_float4(vals[0], vals[1], vals[2], vals[3]);
        }
    }
    __syncthreads();

    // ---- GEMM2: O[t][v] = r~ . S + P . v  (4x4 tile, all-vector loads) ----
    const int t4 = (tid >> 4) * 4;
    const int v4 = (tid & 15) * 4;
    float acc[4][4];
    #pragma unroll
    for (int a = 0; a < 4; a++)
        #pragma unroll
        for (int b = 0; b < 4; b++) acc[a][b] = 0.0f;

    #pragma unroll 8
    for (int kk = 0; kk < Kk; kk++) {
        float4 ra = *(const float4*)&sm.rT[kk][t4];
        float4 sv = *(const float4*)&sm.S[kk][v4];
        float rr[4] = {ra.x, ra.y, ra.z, ra.w};
        float ss[4] = {sv.x, sv.y, sv.z, sv.w};
        #pragma unroll
        for (int a = 0; a < 4; a++)
            #pragma unroll
            for (int b = 0; b < 4; b++)
                acc[a][b] = fmaf(rr[a], ss[b], acc[a][b]);
    }
    #pragma unroll 8
    for (int j = 0; j < Cc; j++) {
        float4 pa = *(const float4*)&sm.wp.PT[j][t4];
        float4 vv = *(const float4*)&sm.v[j][v4];
        float pp[4] = {pa.x, pa.y, pa.z, pa.w};
        float vr[4] = {vv.x, vv.y, vv.z, vv.w};
        #pragma unroll
        for (int a = 0; a < 4; a++)
            #pragma unroll
            for (int b = 0; b < 4; b++)
                acc[a][b] = fmaf(pp[a], vr[b], acc[a][b]);
    }

    float* op = out + ((size_t)bh * Tt + t0) * Vv;
    #pragma unroll
    for (int a = 0; a < 4; a++)
        *(float4*)&op[(size_t)(t4 + a) * Vv + v4] =
            make_float4(acc[a][0], acc[a][1], acc[a][2], acc[a][3]);
}

// ---------------- launch ----------------
extern "C" void kernel_launch(void* const* d_in, const int* in_sizes, int n_in,
                              void* d_out, int out_size)
{
    const float* r  = (const float*)d_in[0];
    const float* k  = (const float*)d_in[1];
    const float* v  = (const float*)d_in[2];
    const float* w  = (const float*)d_in[3];
    const float* u  = (const float*)d_in[4];
    const float* st = (const float*)d_in[5];
    float* out = (float*)d_out;

    static bool configured = false;
    if (!configured) {
        cudaFuncSetAttribute(k1_chunk, cudaFuncAttributeMaxDynamicSharedMemorySize,
                             (int)sizeof(K1Smem));
        cudaFuncSetAttribute(k3_out, cudaFuncAttributeMaxDynamicSharedMemorySize,
                             (int)sizeof(K3Smem));
        configured = true;
    }

    k1_chunk<<<dim3(NCk, BH), 256, sizeof(K1Smem)>>>(k, v, w);
    k2_scan<<<dim3(4, BH), 256>>>(st, out);
    k3_out<<<dim3(NCk, BH), 256, sizeof(K3Smem)>>>(r, k, v, w, u, out);
}

// round 5
// speedup vs baseline: 1.6400x; 1.1295x over previous
#include <cuda_runtime.h>

// Problem constants
#define Bb 2
#define Hh 16
#define Tt 2048
#define Kk 64
#define Vv 64
#define Cc 64                 // chunk length
#define NCk (Tt/Cc)           // 32 chunks
#define BH (Bb*Hh)            // 32
#define OUT_T_SIZE (BH*Tt*Vv) // floats of 'out' before state_f

// ---------------- scratch (static __device__, no allocation) ----------------
__device__ float g_aC[BH*NCk*Kk];                   // chunk total decay     256KB
__device__ float g_dS[(size_t)BH*NCk*Kk*Vv];        // chunk state delta     16MB
__device__ float g_Sc[(size_t)BH*NCk*Kk*Vv];        // state at chunk start  16MB

// 4 independent warp-inclusive product scans (componentwise over lanes)
__device__ __forceinline__ float4 warp_prod_scan4(float4 a) {
    const int lane = threadIdx.x & 31;
    #pragma unroll
    for (int off = 1; off < 32; off <<= 1) {
        float x0 = __shfl_up_sync(0xffffffffu, a.x, off);
        float x1 = __shfl_up_sync(0xffffffffu, a.y, off);
        float x2 = __shfl_up_sync(0xffffffffu, a.z, off);
        float x3 = __shfl_up_sync(0xffffffffu, a.w, off);
        if (lane >= off) { a.x *= x0; a.y *= x1; a.z *= x2; a.w *= x3; }
    }
    return a;
}
__device__ __forceinline__ float4 shfl_up1_or_one4(float4 a) {
    const int lane = threadIdx.x & 31;
    float4 r;
    r.x = __shfl_up_sync(0xffffffffu, a.x, 1);
    r.y = __shfl_up_sync(0xffffffffu, a.y, 1);
    r.z = __shfl_up_sync(0xffffffffu, a.z, 1);
    r.w = __shfl_up_sync(0xffffffffu, a.w, 1);
    if (lane == 0) r = make_float4(1.f, 1.f, 1.f, 1.f);
    return r;
}
__device__ __forceinline__ float4 shfl31_4(float4 a) {
    float4 r;
    r.x = __shfl_sync(0xffffffffu, a.x, 31);
    r.y = __shfl_sync(0xffffffffu, a.y, 31);
    r.z = __shfl_sync(0xffffffffu, a.z, 31);
    r.w = __shfl_sync(0xffffffffu, a.w, 31);
    return r;
}

// ================= kernel 1: suffix decays + delta-state GEMM =================
// dS[k][v] = sum_i sfx_i[k] * k_i[k] * v_i[v],  sfx_i = prod_{j=i+1..63} w_j (<=1, safe)
struct K1Smem {
    float w[Cc][68];
    float k[Cc][68];   // raw k -> sfx*k in place
    float v[Cc][Vv];
};

__global__ __launch_bounds__(256) void k1_chunk(
    const float* __restrict__ k, const float* __restrict__ v,
    const float* __restrict__ w)
{
    extern __shared__ char smem_raw[];
    K1Smem& sm = *reinterpret_cast<K1Smem*>(smem_raw);

    const int c  = blockIdx.x;
    const int bh = blockIdx.y;
    const int h  = bh & (Hh - 1);
    const int t0 = c * Cc;

    const int tid  = threadIdx.x;
    const int lane = tid & 31;
    const int wi   = tid >> 5;

    // ---- stage w, k, v (coalesced float4) ----
    {
        const float4* wp = (const float4*)(w + ((size_t)h  * Tt + t0) * Kk);
        const float4* kp = (const float4*)(k + ((size_t)bh * Tt + t0) * Kk);
        const float4* vp = (const float4*)(v + ((size_t)bh * Tt + t0) * Vv);
        #pragma unroll
        for (int i = tid; i < Cc * Kk / 4; i += 256) {
            int t = i >> 4, k0 = (i & 15) * 4;
            *(float4*)&sm.w[t][k0] = wp[i];
            *(float4*)&sm.k[t][k0] = kp[i];
            ((float4*)sm.v)[i]     = vp[i];
        }
    }
    __syncthreads();

    // ---- vec4 suffix scan: each warp owns 8 k-columns (2 groups of 4) ----
    #pragma unroll
    for (int g = 0; g < 2; g++) {
        const int kk4 = wi * 8 + g * 4;
        // half A: rows 63..32 (reversed)
        float4 wA = *(const float4*)&sm.w[63 - lane][kk4];
        wA.x = fmaxf(wA.x, 1e-6f); wA.y = fmaxf(wA.y, 1e-6f);
        wA.z = fmaxf(wA.z, 1e-6f); wA.w = fmaxf(wA.w, 1e-6f);
        float4 sA   = warp_prod_scan4(wA);          // prod rows [63-lane..63]
        float4 sfxA = shfl_up1_or_one4(sA);
        float4 T0   = shfl31_4(sA);                 // prod rows [32..63]
        float4 kA = *(const float4*)&sm.k[63 - lane][kk4];
        kA.x *= sfxA.x; kA.y *= sfxA.y; kA.z *= sfxA.z; kA.w *= sfxA.w;
        *(float4*)&sm.k[63 - lane][kk4] = kA;
        // half B: rows 31..0 (reversed)
        float4 wB = *(const float4*)&sm.w[31 - lane][kk4];
        wB.x = fmaxf(wB.x, 1e-6f); wB.y = fmaxf(wB.y, 1e-6f);
        wB.z = fmaxf(wB.z, 1e-6f); wB.w = fmaxf(wB.w, 1e-6f);
        float4 sB   = warp_prod_scan4(wB);          // prod rows [31-lane..31]
        float4 sfxB = shfl_up1_or_one4(sB);
        float4 kB = *(const float4*)&sm.k[31 - lane][kk4];
        kB.x *= sfxB.x * T0.x; kB.y *= sfxB.y * T0.y;
        kB.z *= sfxB.z * T0.z; kB.w *= sfxB.w * T0.w;
        *(float4*)&sm.k[31 - lane][kk4] = kB;
        if (lane == 31) {
            float4 aC;
            aC.x = sB.x * T0.x; aC.y = sB.y * T0.y;
            aC.z = sB.z * T0.z; aC.w = sB.w * T0.w;
            *(float4*)&g_aC[(bh * NCk + c) * Kk + kk4] = aC;
        }
    }
    __syncthreads();

    // ---- delta-state GEMM (64k x 64v over 64t), 4x4 tile per thread ----
    const int tk = (tid >> 4) * 4;
    const int tv = (tid & 15) * 4;
    float acc[4][4];
    #pragma unroll
    for (int a = 0; a < 4; a++)
        #pragma unroll
        for (int b = 0; b < 4; b++) acc[a][b] = 0.0f;

    #pragma unroll 8
    for (int t = 0; t < Cc; t++) {
        float4 ka = *(const float4*)&sm.k[t][tk];
        float4 va = *(const float4*)&sm.v[t][tv];
        float kr[4] = {ka.x, ka.y, ka.z, ka.w};
        float vr[4] = {va.x, va.y, va.z, va.w};
        #pragma unroll
        for (int a = 0; a < 4; a++)
            #pragma unroll
            for (int b = 0; b < 4; b++)
                acc[a][b] = fmaf(kr[a], vr[b], acc[a][b]);
    }

    float* dsp = g_dS + (size_t)(bh * NCk + c) * Kk * Vv;
    #pragma unroll
    for (int a = 0; a < 4; a++)
        *(float4*)&dsp[(size_t)(tk + a) * Vv + tv] =
            make_float4(acc[a][0], acc[a][1], acc[a][2], acc[a][3]);
}

// ================= kernel 2: sequential chunk-level state scan =================
__global__ __launch_bounds__(256) void k2_scan(
    const float* __restrict__ state_in, float* __restrict__ out)
{
    const int bh  = blockIdx.y;
    const int tid = threadIdx.x;
    const int fi  = blockIdx.x * 256 + tid;    // float4 index in [0,1024)
    const int krow = fi >> 4;

    float4 S = ((const float4*)(state_in + (size_t)bh * Kk * Vv))[fi];

    const float*  aCb = g_aC + bh * NCk * Kk;
    const float4* dSb = (const float4*)(g_dS + (size_t)bh * NCk * Kk * Vv);
    float4*       Scb = (float4*)(g_Sc + (size_t)bh * NCk * Kk * Vv);

    float4 db[2][4];
    float  ab[2][4];

    #pragma unroll
    for (int j = 0; j < 4; j++) {
        db[0][j] = dSb[(size_t)j * 1024 + fi];
        ab[0][j] = aCb[j * Kk + krow];
    }

    #pragma unroll 1
    for (int g = 0; g < NCk / 4; g++) {
        const int cur = g & 1;
        if (g + 1 < NCk / 4) {
            #pragma unroll
            for (int j = 0; j < 4; j++) {
                int c = (g + 1) * 4 + j;
                db[cur ^ 1][j] = dSb[(size_t)c * 1024 + fi];
                ab[cur ^ 1][j] = aCb[c * Kk + krow];
            }
        }
        #pragma unroll
        for (int j = 0; j < 4; j++) {
            int c = g * 4 + j;
            Scb[(size_t)c * 1024 + fi] = S;
            float a = ab[cur][j]; float4 d = db[cur][j];
            S.x = fmaf(a, S.x, d.x); S.y = fmaf(a, S.y, d.y);
            S.z = fmaf(a, S.z, d.z); S.w = fmaf(a, S.w, d.w);
        }
    }

    ((float4*)(out + (size_t)OUT_T_SIZE + (size_t)bh * Kk * Vv))[fi] = S;
}

// ================= kernel 3: outputs =================
// Mid-chunk normalization m = prod(rows 0..31) per k-column:
//   r~_i = r_i * prefix_i          (<=1; cross-chunk S term)
//   r^_i = r~_i / m                (bounded)
//   k^_j = k_j * m / incl_j        (bounded)
//   P[i][j] = r^_i . k^_j (j<i), diag_i (j==i), 0 (j>i);  O = r~.S + P.v
struct K3Smem {
    float S[Kk][Vv];                                        // 16384
    float rT[Kk][68];                                       // 17408
    union { float kT[Kk][68]; float v[Cc][Vv]; } kv;        // 17408
    union { float wT[Kk][68]; float rh[Kk][68];
            float PT[Cc][68]; } wp;                         // 17408 (time-phased)
    float dp[8][66];                                        // 2112
    float diag[Cc];                                         // 256
};

__global__ __launch_bounds__(256) void k3_out(
    const float* __restrict__ r, const float* __restrict__ k,
    const float* __restrict__ v, const float* __restrict__ w,
    const float* __restrict__ u, float* __restrict__ out)
{
    extern __shared__ char smem_raw[];
    K3Smem& sm = *reinterpret_cast<K3Smem*>(smem_raw);

    const int c  = blockIdx.x;
    const int bh = blockIdx.y;
    const int h  = bh & (Hh - 1);
    const int t0 = c * Cc;

    const int tid  = threadIdx.x;
    const int lane = tid & 31;
    const int wi   = tid >> 5;

    // ---- stage chunk-start state ----
    {
        const float4* Sp = (const float4*)(g_Sc + (size_t)(bh * NCk + c) * Kk * Vv);
        #pragma unroll
        for (int p = 0; p < 4; p++) {
            int f = p * 256 + tid;
            float4 x = Sp[f];
            int kr = f >> 4, v0 = (f & 15) * 4;
            *(float4*)&sm.S[kr][v0] = x;
        }
    }
    // ---- stage r,k,w transposed (k-major); v comes later ----
    {
        const float4* rp = (const float4*)(r + ((size_t)bh * Tt + t0) * Kk);
        const float4* kp = (const float4*)(k + ((size_t)bh * Tt + t0) * Kk);
        const float4* wp = (const float4*)(w + ((size_t)h  * Tt + t0) * Kk);
        #pragma unroll
        for (int i = tid; i < Cc * Kk / 4; i += 256) {
            int t = i >> 4, k0 = (i & 15) * 4;
            float4 rx = rp[i], kx = kp[i], wx = wp[i];
            sm.rT[k0 + 0][t] = rx.x; sm.rT[k0 + 1][t] = rx.y;
            sm.rT[k0 + 2][t] = rx.z; sm.rT[k0 + 3][t] = rx.w;
            sm.kv.kT[k0 + 0][t] = kx.x; sm.kv.kT[k0 + 1][t] = kx.y;
            sm.kv.kT[k0 + 2][t] = kx.z; sm.kv.kT[k0 + 3][t] = kx.w;
            sm.wp.wT[k0 + 0][t] = wx.x; sm.wp.wT[k0 + 1][t] = wx.y;
            sm.wp.wT[k0 + 2][t] = wx.z; sm.wp.wT[k0 + 3][t] = wx.w;
        }
    }
    __syncthreads();

    // ---- vec4 prefix scan + normalize: each warp owns 8 k-columns ----
    {
        float dA = 0.0f, dB = 0.0f;
        #pragma unroll
        for (int g = 0; g < 2; g++) {
            const int kk4 = wi * 8 + g * 4;
            float4 uv = *(const float4*)&u[h * Kk + kk4];
            float uu[4]  = {uv.x, uv.y, uv.z, uv.w};
            // read both halves of w for all 4 columns BEFORE any union write
            float w0c[4], w1c[4];
            #pragma unroll
            for (int cc = 0; cc < 4; cc++) {
                w0c[cc] = fmaxf(sm.wp.wT[kk4 + cc][lane],      1e-6f);
                w1c[cc] = fmaxf(sm.wp.wT[kk4 + cc][32 + lane], 1e-6f);
            }
            float4 p = warp_prod_scan4(make_float4(w0c[0], w0c[1], w0c[2], w0c[3]));
            float4 q = warp_prod_scan4(make_float4(w1c[0], w1c[1], w1c[2], w1c[3]));
            float4 m    = shfl31_4(p);          // prod rows 0..31
            float4 pre  = shfl_up1_or_one4(p);
            float4 pre2 = shfl_up1_or_one4(q);
            float pa[4]   = {p.x, p.y, p.z, p.w};
            float qa[4]   = {q.x, q.y, q.z, q.w};
            float ma[4]   = {m.x, m.y, m.z, m.w};
            float prea[4] = {pre.x, pre.y, pre.z, pre.w};
            float pr2a[4] = {pre2.x, pre2.y, pre2.z, pre2.w};
            #pragma unroll
            for (int cc = 0; cc < 4; cc++) {
                const int kk = kk4 + cc;
                // half 0: rows 0..31
                float rv = sm.rT[kk][lane];
                float kv = sm.kv.kT[kk][lane];
                dA = fmaf(rv * kv, uu[cc], dA);
                float rt_ = rv * prea[cc];
                sm.rT[kk][lane]     = rt_;
                sm.wp.rh[kk][lane]  = rt_ / ma[cc];             // overwrites wT (already read)
                sm.kv.kT[kk][lane]  = kv * ma[cc] / pa[cc];
                // half 1: rows 32..63
                float rv2 = sm.rT[kk][32 + lane];
                float kv2 = sm.kv.kT[kk][32 + lane];
                dB = fmaf(rv2 * kv2, uu[cc], dB);
                sm.rT[kk][32 + lane]    = rv2 * (ma[cc] * pr2a[cc]);  // r~
                sm.wp.rh[kk][32 + lane] = rv2 * pr2a[cc];             // r~/m
                sm.kv.kT[kk][32 + lane] = kv2 / qa[cc];               // k*m/(m*q)
            }
        }
        sm.dp[wi][lane]      = dA;
        sm.dp[wi][32 + lane] = dB;
    }
    __syncthreads();
    if (tid < Cc) {
        float d = 0.0f;
        #pragma unroll
        for (int j = 0; j < 8; j++) d += sm.dp[j][tid];
        sm.diag[tid] = d;
    }
    __syncthreads();

    // ---- GEMM1: P[i][j] = r^_i . k^_j  (4x4 tile) ----
    const int i4 = (tid >> 4) * 4;      // t rows
    const int j4 = (tid & 15) * 4;      // tau cols
    float acc[4][4];
    #pragma unroll
    for (int a = 0; a < 4; a++)
        #pragma unroll
        for (int b = 0; b < 4; b++) acc[a][b] = 0.0f;

    #pragma unroll 8
    for (int kk = 0; kk < Kk; kk++) {
        float4 ra = *(const float4*)&sm.wp.rh[kk][i4];
        float4 kb = *(const float4*)&sm.kv.kT[kk][j4];
        float rr[4] = {ra.x, ra.y, ra.z, ra.w};
        float kc[4] = {kb.x, kb.y, kb.z, kb.w};
        #pragma unroll
        for (int a = 0; a < 4; a++)
            #pragma unroll
            for (int b = 0; b < 4; b++)
                acc[a][b] = fmaf(rr[a], kc[b], acc[a][b]);
    }
    // preload v into registers while other warps finish GEMM1
    float4 vreg[4];
    {
        const float4* vp = (const float4*)(v + ((size_t)bh * Tt + t0) * Vv);
        #pragma unroll
        for (int p = 0; p < 4; p++) vreg[p] = vp[p * 256 + tid];
    }
    float dg[4];
    #pragma unroll
    for (int a = 0; a < 4; a++) dg[a] = sm.diag[i4 + a];

    __syncthreads();   // all reads of rh/kT complete

    // write masked P^T (into wp union) and v (into kv union)
    #pragma unroll
    for (int b = 0; b < 4; b++) {
        int j = j4 + b;
        float vals[4];
        #pragma unroll
        for (int a = 0; a < 4; a++) {
            int i = i4 + a;
            vals[a] = (j < i) ? acc[a][b] : ((j == i) ? dg[a] : 0.0f);
        }
        *(float4*)&sm.wp.PT[j][i4] = make_float4(vals[0], vals[1], vals[2], vals[3]);
    }
    #pragma unroll
    for (int p = 0; p < 4; p++) ((float4*)sm.kv.v)[p * 256 + tid] = vreg[p];
    __syncthreads();

    // ---- GEMM2: O[t][v] = r~ . S + P . v  (4x4 tile, all-vector loads) ----
    const int t4 = i4;
    const int v4 = j4;
    #pragma unroll
    for (int a = 0; a < 4; a++)
        #pragma unroll
        for (int b = 0; b < 4; b++) acc[a][b] = 0.0f;

    #pragma unroll 8
    for (int kk = 0; kk < Kk; kk++) {
        float4 ra = *(const float4*)&sm.rT[kk][t4];
        float4 sv = *(const float4*)&sm.S[kk][v4];
        float rr[4] = {ra.x, ra.y, ra.z, ra.w};
        float ss[4] = {sv.x, sv.y, sv.z, sv.w};
        #pragma unroll
        for (int a = 0; a < 4; a++)
            #pragma unroll
            for (int b = 0; b < 4; b++)
                acc[a][b] = fmaf(rr[a], ss[b], acc[a][b]);
    }
    #pragma unroll 8
    for (int j = 0; j < Cc; j++) {
        float4 pa = *(const float4*)&sm.wp.PT[j][t4];
        float4 vv = *(const float4*)&sm.kv.v[j][v4];
        float pp[4] = {pa.x, pa.y, pa.z, pa.w};
        float vr[4] = {vv.x, vv.y, vv.z, vv.w};
        #pragma unroll
        for (int a = 0; a < 4; a++)
            #pragma unroll
            for (int b = 0; b < 4; b++)
                acc[a][b] = fmaf(pp[a], vr[b], acc[a][b]);
    }

    float* op = out + ((size_t)bh * Tt + t0) * Vv;
    #pragma unroll
    for (int a = 0; a < 4; a++)
        *(float4*)&op[(size_t)(t4 + a) * Vv + v4] =
            make_float4(acc[a][0], acc[a][1], acc[a][2], acc[a][3]);
}

// ---------------- launch ----------------
extern "C" void kernel_launch(void* const* d_in, const int* in_sizes, int n_in,
                              void* d_out, int out_size)
{
    const float* r  = (const float*)d_in[0];
    const float* k  = (const float*)d_in[1];
    const float* v  = (const float*)d_in[2];
    const float* w  = (const float*)d_in[3];
    const float* u  = (const float*)d_in[4];
    const float* st = (const float*)d_in[5];
    float* out = (float*)d_out;

    static bool configured = false;
    if (!configured) {
        cudaFuncSetAttribute(k1_chunk, cudaFuncAttributeMaxDynamicSharedMemorySize,
                             (int)sizeof(K1Smem));
        cudaFuncSetAttribute(k3_out, cudaFuncAttributeMaxDynamicSharedMemorySize,
                             (int)sizeof(K3Smem));
        configured = true;
    }

    k1_chunk<<<dim3(NCk, BH), 256, sizeof(K1Smem)>>>(k, v, w);
    k2_scan<<<dim3(4, BH), 256>>>(st, out);
    k3_out<<<dim3(NCk, BH), 256, sizeof(K3Smem)>>>(r, k, v, w, u, out);
}